// round 15
// baseline (speedup 1.0000x reference)
#include <cuda_runtime.h>
#include <cstdint>

// GIN_38216619000492: GINConv (eps=0) + 2-layer MLP.
//   h = x + segment_sum(x[src], dst);  hid = relu(h@W1+b1);  out = hid@W2+b2
// N=50000, E=800000, edge_index int32. MLP via mma.sync tf32 (base sm_100).
// R14: dst-range split + stream fork-join so scatter[half2] (L2-atomic-bound)
// overlaps mlp[half1] (tensor/latency-bound). Kernel bodies = R13 proven,
// parameterized by range only.
//   main: init -> scat[0,Nh) -> evA -> scat[Nh,N) -> mlp[Nh,N) -> wait(evC)
//   s2  : wait(evA) -> mlp[0,Nh) -> evC

#define D_IN  64
#define D_H   256
#define D_OUT 64
#define NMAX  50000

static __device__ float g_h[(size_t)NMAX * D_IN];
static __device__ float g_B1[17408];   // W1^T tf32 image: [n=256][k=64], stride 68
static __device__ float g_B2[16640];   // W2^T tf32 image: [n=64][k=256], stride 260

__device__ __forceinline__ uint32_t f2tf32(float f) {
    uint32_t u;
    asm("cvt.rna.tf32.f32 %0, %1;" : "=r"(u) : "f"(f));
    return u;
}

__device__ __forceinline__ void mma8(float* c, uint32_t a0, uint32_t a1,
                                     uint32_t a2, uint32_t a3,
                                     uint32_t b0, uint32_t b1) {
    asm volatile(
        "mma.sync.aligned.m16n8k8.row.col.f32.tf32.tf32.f32 "
        "{%0,%1,%2,%3}, {%4,%5,%6,%7}, {%8,%9}, {%0,%1,%2,%3};"
        : "+f"(c[0]), "+f"(c[1]), "+f"(c[2]), "+f"(c[3])
        : "r"(a0), "r"(a1), "r"(a2), "r"(a3), "r"(b0), "r"(b1));
}

// ---------------------------------------------------------------------------
// Kernel 1: zero g_h + build tf32 weight images (single launch).
// ---------------------------------------------------------------------------
__global__ void gin_init(const float* __restrict__ W1,
                         const float* __restrict__ W2, int n4) {
    int i = blockIdx.x * blockDim.x + threadIdx.x;
    if (i < n4) ((float4*)g_h)[i] = make_float4(0.f, 0.f, 0.f, 0.f);
    if (i < 16384) {                        // W1[k][n], k<64, n<256
        int k = i >> 8, n = i & 255;
        ((uint32_t*)g_B1)[n * 68 + k] = f2tf32(W1[i]);
    } else if (i < 32768) {                 // W2[k][n], k<256, n<64
        int j = i - 16384;
        int k = j >> 6, n = j & 63;
        ((uint32_t*)g_B2)[n * 260 + k] = f2tf32(W2[j]);
    }
}

// ---------------------------------------------------------------------------
// Kernel 2: scatter-add for dst in [dstLo, dstHi). red.global.add.v4.f32,
// 16 threads/edge (R13-proven body + range predicate).
// ---------------------------------------------------------------------------
__global__ void gin_scatter(const float* __restrict__ x,
                            const int* __restrict__ ei, int E,
                            int dstLo, int dstHi) {
    int w = blockIdx.x * blockDim.x + threadIdx.x;
    int e = w >> 4;
    if (e >= E) return;
    int dst = ei[E + e];
    if (dst < dstLo || dst >= dstHi) return;
    int c = (w & 15) << 2;
    int src = ei[e];
    float4 v = *(const float4*)(x + (size_t)src * D_IN + c);
    float* o = g_h + (size_t)dst * D_IN + c;
    asm volatile("red.global.add.v4.f32 [%0], {%1, %2, %3, %4};"
                 :: "l"(o), "f"(v.x), "f"(v.y), "f"(v.z), "f"(v.w)
                 : "memory");
}

// ---------------------------------------------------------------------------
// Kernel 3: fused MLP for rows [rowLo, rowLo + 128*gridDim). EXACT R13/R8
// structure (41.6us proven), staging reads x + g_h.
// SMEM layout (205,568 B, validated):
//   phase1: hs @0 [128][68], B1 @8704 [256][68]
//   phase2: hid rows 0..95 @0 (stride 260), rows 96..127 @42752
//   B2 @26112 [64][260]; b1s @51072; b2s @51328.
// ---------------------------------------------------------------------------
#define HS_F    0
#define B1_F    8704
#define HID0_F  0
#define B2_F    26112
#define HID1_F  42752
#define B1S_F   51072
#define B2S_F   51328
#define SMEM_BYTES (51392 * 4)

__device__ __forceinline__ int hid_off(int r) {
    return (r < 96) ? (HID0_F + r * 260) : (HID1_F + (r - 96) * 260);
}

__global__ __launch_bounds__(512, 1)
void gin_mlp(const float* __restrict__ x,
             const float* __restrict__ b1, const float* __restrict__ b2,
             float* __restrict__ out, int rowLo, int N) {
    extern __shared__ float s[];
    uint32_t* su = (uint32_t*)s;

    const int t = threadIdx.x;
    const int w = t >> 5;
    const int mw = w & 7;         // m-group: rows 16mw..16mw+16
    const int nh = w >> 3;        // n-half
    const int lane = t & 31;
    const int g = lane >> 2;
    const int tg = lane & 3;
    const int row0 = rowLo + blockIdx.x * 128;

    // ---- Stage B1, B2, biases ----
    {
        const float4* g1 = (const float4*)g_B1;
        const float4* g2 = (const float4*)g_B2;
        float4* s1 = (float4*)(s + B1_F);
        float4* s2 = (float4*)(s + B2_F);
        #pragma unroll 4
        for (int i = t; i < 4352; i += 512) s1[i] = g1[i];
        #pragma unroll 4
        for (int i = t; i < 4160; i += 512) s2[i] = g2[i];
        if (t < 64) ((float4*)(s + B1S_F))[t] = ((const float4*)b1)[t];
        if (t < 16) ((float4*)(s + B2S_F))[t] = ((const float4*)b2)[t];
    }

    // ---- Stage A1 = tf32(x + g_h) [128][68] ----
    #pragma unroll 4
    for (int i = t; i < 2048; i += 512) {          // 128 rows x 16 float4
        int r = i >> 4, k4 = (i & 15) << 2;
        float4 v = make_float4(0.f, 0.f, 0.f, 0.f);
        int gr = row0 + r;
        if (gr < N) {
            float4 xv = *(const float4*)(x   + (size_t)gr * D_IN + k4);
            float4 hv = *(const float4*)(g_h + (size_t)gr * D_IN + k4);
            v = make_float4(xv.x + hv.x, xv.y + hv.y, xv.z + hv.z, xv.w + hv.w);
        }
        uint4 u = make_uint4(f2tf32(v.x), f2tf32(v.y), f2tf32(v.z), f2tf32(v.w));
        *(uint4*)(s + HS_F + r * 68 + k4) = u;
    }
    __syncthreads();

    // ---- GEMM1: rows [16mw,16mw+16) x cols [nh*128, nh*128+128) ----
    float acc[16][4];
    #pragma unroll
    for (int nt = 0; nt < 16; nt++)
        #pragma unroll
        for (int j = 0; j < 4; j++) acc[nt][j] = 0.f;

    {
        const uint32_t* arow_lo = su + HS_F + (16 * mw + g) * 68;
        const uint32_t* arow_hi = arow_lo + 8 * 68;
        const uint32_t* Bb = su + B1_F + (nh * 128 + g) * 68;
        #pragma unroll
        for (int ks = 0; ks < 8; ks++) {
            int kb = ks * 8;
            uint32_t a0 = arow_lo[kb + tg];
            uint32_t a1 = arow_hi[kb + tg];
            uint32_t a2 = arow_lo[kb + tg + 4];
            uint32_t a3 = arow_hi[kb + tg + 4];
            #pragma unroll
            for (int c8 = 0; c8 < 2; c8++) {
                uint32_t bv[8][2];
                #pragma unroll
                for (int q = 0; q < 8; q++) {
                    int ntl = c8 * 8 + q;
                    bv[q][0] = Bb[ntl * 8 * 68 + kb + tg];
                    bv[q][1] = Bb[ntl * 8 * 68 + kb + tg + 4];
                }
                #pragma unroll
                for (int q = 0; q < 8; q++)
                    mma8(acc[c8 * 8 + q], a0, a1, a2, a3, bv[q][0], bv[q][1]);
            }
        }
    }
    __syncthreads();   // all reads of hs/B1 done; hid may alias them

    // ---- Epilogue 1: hid = tf32(relu(D1 + b1)) ----
    {
        const int r_lo = 16 * mw + g;
        float* h_lo = s + hid_off(r_lo);
        float* h_hi = s + hid_off(r_lo + 8);
        #pragma unroll
        for (int ntl = 0; ntl < 16; ntl++) {
            int col = (nh * 16 + ntl) * 8 + 2 * tg;
            float bb0 = s[B1S_F + col], bb1 = s[B1S_F + col + 1];
            uint2 u0, u1;
            u0.x = f2tf32(fmaxf(acc[ntl][0] + bb0, 0.f));
            u0.y = f2tf32(fmaxf(acc[ntl][1] + bb1, 0.f));
            u1.x = f2tf32(fmaxf(acc[ntl][2] + bb0, 0.f));
            u1.y = f2tf32(fmaxf(acc[ntl][3] + bb1, 0.f));
            *(uint2*)(h_lo + col) = u0;
            *(uint2*)(h_hi + col) = u1;
        }
    }
    __syncthreads();

    // ---- GEMM2: rows [16mw,16mw+16) x cols [32nh,32nh+32) ----
    float acc2[4][4];
    #pragma unroll
    for (int nt = 0; nt < 4; nt++)
        #pragma unroll
        for (int j = 0; j < 4; j++) acc2[nt][j] = 0.f;

    {
        const uint32_t* arow_lo = su + hid_off(16 * mw + g);
        const uint32_t* arow_hi = su + hid_off(16 * mw + g + 8);
        const uint32_t* Bb = su + B2_F + (nh * 32 + g) * 260;
        #pragma unroll 4
        for (int ks = 0; ks < 32; ks++) {
            int kb = ks * 8;
            uint32_t a0 = arow_lo[kb + tg];
            uint32_t a1 = arow_hi[kb + tg];
            uint32_t a2 = arow_lo[kb + tg + 4];
            uint32_t a3 = arow_hi[kb + tg + 4];
            uint32_t bv[4][2];
            #pragma unroll
            for (int q = 0; q < 4; q++) {
                bv[q][0] = Bb[q * 8 * 260 + kb + tg];
                bv[q][1] = Bb[q * 8 * 260 + kb + tg + 4];
            }
            #pragma unroll
            for (int q = 0; q < 4; q++)
                mma8(acc2[q], a0, a1, a2, a3, bv[q][0], bv[q][1]);
        }
    }

    // ---- Epilogue 2: out = D2 + b2 (fp32) ----
    {
        int gr_lo = row0 + 16 * mw + g;
        int gr_hi = gr_lo + 8;
        #pragma unroll
        for (int ntl = 0; ntl < 4; ntl++) {
            int col = (nh * 4 + ntl) * 8 + 2 * tg;
            float bb0 = s[B2S_F + col], bb1 = s[B2S_F + col + 1];
            if (gr_lo < N) {
                float2 v = make_float2(acc2[ntl][0] + bb0, acc2[ntl][1] + bb1);
                *(float2*)(out + (size_t)gr_lo * D_OUT + col) = v;
            }
            if (gr_hi < N) {
                float2 v = make_float2(acc2[ntl][2] + bb0, acc2[ntl][3] + bb1);
                *(float2*)(out + (size_t)gr_hi * D_OUT + col) = v;
            }
        }
    }
}

// ---------------------------------------------------------------------------
// Launch. Inputs: x[f32], edge_index[i32 2xE], W1, b1, W2, b2.
// Fork-join: scat2 overlaps mlp1 on a second (non-blocking) stream.
// Streams/events created per call and intentionally leaked (a handful of
// harness calls total; destroying capture-referenced objects is unsafe).
// ---------------------------------------------------------------------------
extern "C" void kernel_launch(void* const* d_in, const int* in_sizes, int n_in,
                              void* d_out, int out_size) {
    const float* x  = (const float*)d_in[0];
    const int*   ei = (const int*)d_in[1];
    const float* W1 = (const float*)d_in[2];
    const float* b1 = (const float*)d_in[3];
    const float* W2 = (const float*)d_in[4];
    const float* b2 = (const float*)d_in[5];
    float* out = (float*)d_out;

    const int N = in_sizes[0] / D_IN;   // 50000
    const int E = in_sizes[1] / 2;      // 800000
    const int Nh = 25088;               // 196 tiles of 128 rows

    cudaFuncSetAttribute(gin_mlp, cudaFuncAttributeMaxDynamicSharedMemorySize,
                         SMEM_BYTES);

    cudaStream_t s2 = 0;
    cudaEvent_t evA = 0, evC = 0;
    bool fork_ok =
        (cudaStreamCreateWithFlags(&s2, cudaStreamNonBlocking) == cudaSuccess) &&
        (cudaEventCreateWithFlags(&evA, cudaEventDisableTiming) == cudaSuccess) &&
        (cudaEventCreateWithFlags(&evC, cudaEventDisableTiming) == cudaSuccess);

    int n4 = N * (D_IN / 4);
    int work = E * 16;
    const int g1 = (Nh + 127) / 128;                 // 196 tiles
    const int g2 = (N - Nh + 127) / 128;             // 195 tiles

    gin_init<<<(n4 + 255) / 256, 256>>>(W1, W2, n4);
    gin_scatter<<<(work + 255) / 256, 256>>>(x, ei, E, 0, Nh);

    if (fork_ok) {
        cudaEventRecord(evA, 0);
        gin_scatter<<<(work + 255) / 256, 256>>>(x, ei, E, Nh, N);
        // fork: mlp half 1 depends only on scatter half 1 (+init)
        cudaStreamWaitEvent(s2, evA, 0);
        gin_mlp<<<g1, 512, SMEM_BYTES, s2>>>(x, b1, b2, out, 0, N);
        cudaEventRecord(evC, s2);
        // main: mlp half 2 after scatter half 2
        gin_mlp<<<g2, 512, SMEM_BYTES>>>(x, b1, b2, out, Nh, N);
        cudaStreamWaitEvent(0, evC, 0);   // join
    } else {
        // serial fallback (R13 behavior)
        gin_scatter<<<(work + 255) / 256, 256>>>(x, ei, E, Nh, N);
        gin_mlp<<<g1, 512, SMEM_BYTES>>>(x, b1, b2, out, 0, N);
        gin_mlp<<<g2, 512, SMEM_BYTES>>>(x, b1, b2, out, Nh, N);
    }
}

// round 16
// speedup vs baseline: 1.2914x; 1.2914x over previous
#include <cuda_runtime.h>
#include <cstdint>

// GIN_38216619000492: GINConv (eps=0) + 2-layer MLP.
//   h = x + segment_sum(x[src], dst);  hid = relu(h@W1+b1);  out = hid@W2+b2
// N=50000, E=800000, edge_index int32. MLP via mma.sync tf32 (base sm_100).
// R16: PERSISTENT MLP. Grid = 148 CTAs, 64-row tiles, grid-stride. Weights
// (B1+B2+biases) staged ONCE and resident; hs/hid disjoint (221,440 B smem).
// Removes per-tile weight restaging and wave quantization (R15 measured a
// 15.2us/CTA-slot wave tax). Init zero -> cudaMemsetAsync. Scatter = R13.

#define D_IN  64
#define D_H   256
#define D_OUT 64
#define NMAX  50000

static __device__ float g_h[(size_t)NMAX * D_IN];
static __device__ float g_B1[17408];   // W1^T tf32 image: [n=256][k=64], stride 68
static __device__ float g_B2[16640];   // W2^T tf32 image: [n=64][k=256], stride 260

__device__ __forceinline__ uint32_t f2tf32(float f) {
    uint32_t u;
    asm("cvt.rna.tf32.f32 %0, %1;" : "=r"(u) : "f"(f));
    return u;
}

__device__ __forceinline__ void mma8(float* c, uint32_t a0, uint32_t a1,
                                     uint32_t a2, uint32_t a3,
                                     uint32_t b0, uint32_t b1) {
    asm volatile(
        "mma.sync.aligned.m16n8k8.row.col.f32.tf32.tf32.f32 "
        "{%0,%1,%2,%3}, {%4,%5,%6,%7}, {%8,%9}, {%0,%1,%2,%3};"
        : "+f"(c[0]), "+f"(c[1]), "+f"(c[2]), "+f"(c[3])
        : "r"(a0), "r"(a1), "r"(a2), "r"(a3), "r"(b0), "r"(b1));
}

// ---------------------------------------------------------------------------
// Kernel 1: build tf32 weight images (g_h zeroed by cudaMemsetAsync).
// ---------------------------------------------------------------------------
__global__ void gin_prep(const float* __restrict__ W1,
                         const float* __restrict__ W2) {
    int i = blockIdx.x * blockDim.x + threadIdx.x;
    if (i < 16384) {                        // W1[k][n], k<64, n<256
        int k = i >> 8, n = i & 255;
        ((uint32_t*)g_B1)[n * 68 + k] = f2tf32(W1[i]);
    } else if (i < 32768) {                 // W2[k][n], k<256, n<64
        int j = i - 16384;
        int k = j >> 6, n = j & 63;
        ((uint32_t*)g_B2)[n * 260 + k] = f2tf32(W2[j]);
    }
}

// ---------------------------------------------------------------------------
// Kernel 2: scatter-add, red.global.add.v4.f32, 16 threads/edge (R13-proven;
// at the L2 atomic-op floor).
// ---------------------------------------------------------------------------
__global__ void gin_scatter(const float* __restrict__ x,
                            const int* __restrict__ ei, int E) {
    int w = blockIdx.x * blockDim.x + threadIdx.x;
    int e = w >> 4;
    if (e >= E) return;
    int c = (w & 15) << 2;
    int src = ei[e];
    int dst = ei[E + e];
    float4 v = *(const float4*)(x + (size_t)src * D_IN + c);
    float* o = g_h + (size_t)dst * D_IN + c;
    asm volatile("red.global.add.v4.f32 [%0], {%1, %2, %3, %4};"
                 :: "l"(o), "f"(v.x), "f"(v.y), "f"(v.z), "f"(v.w)
                 : "memory");
}

// ---------------------------------------------------------------------------
// Kernel 3: PERSISTENT fused MLP. 148 CTAs x 512 thr; 64-row tiles,
// grid-stride over 782 tiles. Weights resident; per-tile: stage hs, bar,
// GEMM1, epi1->hid, bar, GEMM2, epi2->out.
// Warp w: mq=w&3 (rows [16mq,+16)), nc=w>>2:
//   GEMM1 cols [64nc,+64) (8 n-tiles); GEMM2 cols [16nc,+16) (2 n-tiles).
// SMEM (floats, fully disjoint, 55,360 w = 221,440 B):
//   B1 @0 [256][68]; B2 @17408 [64][260]; b1s @34048; b2s @34304;
//   hs @34368 [64][68]; hid @38720 [64][260].
// ---------------------------------------------------------------------------
#define B1_F    0
#define B2_F    17408
#define B1S_F   34048
#define B2S_F   34304
#define HS_F    34368
#define HID_F   38720
#define SMEM_BYTES (55360 * 4)

__global__ __launch_bounds__(512, 1)
void gin_mlp(const float* __restrict__ x,
             const float* __restrict__ b1, const float* __restrict__ b2,
             float* __restrict__ out, int N, int nTiles) {
    extern __shared__ float s[];
    uint32_t* su = (uint32_t*)s;

    const int t = threadIdx.x;
    const int w = t >> 5;
    const int mq = w & 3;
    const int nc = w >> 2;
    const int lane = t & 31;
    const int g = lane >> 2;
    const int tg = lane & 3;

    // ---- Stage weights + biases ONCE ----
    {
        const float4* g1 = (const float4*)g_B1;
        const float4* g2 = (const float4*)g_B2;
        float4* s1 = (float4*)(s + B1_F);
        float4* s2 = (float4*)(s + B2_F);
        for (int i = t; i < 4352; i += 512) s1[i] = g1[i];
        for (int i = t; i < 4160; i += 512) s2[i] = g2[i];
        if (t < 64) ((float4*)(s + B1S_F))[t] = ((const float4*)b1)[t];
        if (t < 16) ((float4*)(s + B2S_F))[t] = ((const float4*)b2)[t];
    }

    // pointers invariant across tiles
    const uint32_t* arow_lo1 = su + HS_F + (16 * mq + g) * 68;
    const uint32_t* arow_hi1 = arow_lo1 + 8 * 68;
    const uint32_t* Bb1 = su + B1_F + (nc * 64 + g) * 68;
    const uint32_t* arow_lo2 = su + HID_F + (16 * mq + g) * 260;
    const uint32_t* arow_hi2 = arow_lo2 + 8 * 260;
    const uint32_t* Bb2 = su + B2_F + (nc * 16 + g) * 260;

    for (int tile = blockIdx.x; tile < nTiles; tile += gridDim.x) {
        const int row0 = tile * 64;

        // ---- Stage hs = tf32(x + g_h) [64][68] ----
        #pragma unroll
        for (int i = t; i < 1024; i += 512) {       // 64 rows x 16 float4
            int r = i >> 4, k4 = (i & 15) << 2;
            float4 v = make_float4(0.f, 0.f, 0.f, 0.f);
            int gr = row0 + r;
            if (gr < N) {
                float4 xv = *(const float4*)(x   + (size_t)gr * D_IN + k4);
                float4 hv = *(const float4*)(g_h + (size_t)gr * D_IN + k4);
                v = make_float4(xv.x + hv.x, xv.y + hv.y, xv.z + hv.z, xv.w + hv.w);
            }
            uint4 u = make_uint4(f2tf32(v.x), f2tf32(v.y), f2tf32(v.z), f2tf32(v.w));
            *(uint4*)(s + HS_F + r * 68 + k4) = u;
        }
        __syncthreads();   // hs staged (and, on tile 0, weights staged)

        // ---- GEMM1: rows [16mq,+16) x cols [64nc,+64) ----
        float acc[8][4];
        #pragma unroll
        for (int nt = 0; nt < 8; nt++)
            #pragma unroll
            for (int j = 0; j < 4; j++) acc[nt][j] = 0.f;

        #pragma unroll
        for (int ks = 0; ks < 8; ks++) {
            int kb = ks * 8;
            uint32_t a0 = arow_lo1[kb + tg];
            uint32_t a1 = arow_hi1[kb + tg];
            uint32_t a2 = arow_lo1[kb + tg + 4];
            uint32_t a3 = arow_hi1[kb + tg + 4];
            #pragma unroll
            for (int c4 = 0; c4 < 2; c4++) {
                uint32_t bv[4][2];
                #pragma unroll
                for (int q = 0; q < 4; q++) {
                    int ntl = c4 * 4 + q;
                    bv[q][0] = Bb1[ntl * 8 * 68 + kb + tg];
                    bv[q][1] = Bb1[ntl * 8 * 68 + kb + tg + 4];
                }
                #pragma unroll
                for (int q = 0; q < 4; q++)
                    mma8(acc[c4 * 4 + q], a0, a1, a2, a3, bv[q][0], bv[q][1]);
            }
        }

        // ---- Epilogue 1: hid = tf32(relu(D1 + b1)) (hid disjoint from hs) ----
        {
            float* h_lo = s + HID_F + (16 * mq + g) * 260;
            float* h_hi = h_lo + 8 * 260;
            #pragma unroll
            for (int ntl = 0; ntl < 8; ntl++) {
                int col = nc * 64 + ntl * 8 + 2 * tg;
                float bb0 = s[B1S_F + col], bb1 = s[B1S_F + col + 1];
                uint2 u0, u1;
                u0.x = f2tf32(fmaxf(acc[ntl][0] + bb0, 0.f));
                u0.y = f2tf32(fmaxf(acc[ntl][1] + bb1, 0.f));
                u1.x = f2tf32(fmaxf(acc[ntl][2] + bb0, 0.f));
                u1.y = f2tf32(fmaxf(acc[ntl][3] + bb1, 0.f));
                *(uint2*)(h_lo + col) = u0;
                *(uint2*)(h_hi + col) = u1;
            }
        }
        __syncthreads();   // hid complete before cross-warp GEMM2 reads

        // ---- GEMM2: rows [16mq,+16) x cols [16nc,+16) ----
        float acc2[2][4];
        #pragma unroll
        for (int nt = 0; nt < 2; nt++)
            #pragma unroll
            for (int j = 0; j < 4; j++) acc2[nt][j] = 0.f;

        #pragma unroll 4
        for (int ks = 0; ks < 32; ks++) {
            int kb = ks * 8;
            uint32_t a0 = arow_lo2[kb + tg];
            uint32_t a1 = arow_hi2[kb + tg];
            uint32_t a2 = arow_lo2[kb + tg + 4];
            uint32_t a3 = arow_hi2[kb + tg + 4];
            uint32_t bv[2][2];
            #pragma unroll
            for (int q = 0; q < 2; q++) {
                bv[q][0] = Bb2[q * 8 * 260 + kb + tg];
                bv[q][1] = Bb2[q * 8 * 260 + kb + tg + 4];
            }
            #pragma unroll
            for (int q = 0; q < 2; q++)
                mma8(acc2[q], a0, a1, a2, a3, bv[q][0], bv[q][1]);
        }

        // ---- Epilogue 2: out = D2 + b2 (fp32) ----
        {
            int gr_lo = row0 + 16 * mq + g;
            int gr_hi = gr_lo + 8;
            #pragma unroll
            for (int ntl = 0; ntl < 2; ntl++) {
                int col = nc * 16 + ntl * 8 + 2 * tg;
                float bb0 = s[B2S_F + col], bb1 = s[B2S_F + col + 1];
                if (gr_lo < N) {
                    float2 v = make_float2(acc2[ntl][0] + bb0, acc2[ntl][1] + bb1);
                    *(float2*)(out + (size_t)gr_lo * D_OUT + col) = v;
                }
                if (gr_hi < N) {
                    float2 v = make_float2(acc2[ntl][2] + bb0, acc2[ntl][3] + bb1);
                    *(float2*)(out + (size_t)gr_hi * D_OUT + col) = v;
                }
            }
        }
        // no bar: next tile's hs staging is disjoint from hid (GEMM2 reads);
        // all GEMM1 hs-readers passed the epi1 bar already.
    }
}

// ---------------------------------------------------------------------------
// Launch. Inputs: x[f32], edge_index[i32 2xE], W1, b1, W2, b2.
// ---------------------------------------------------------------------------
extern "C" void kernel_launch(void* const* d_in, const int* in_sizes, int n_in,
                              void* d_out, int out_size) {
    const float* x  = (const float*)d_in[0];
    const int*   ei = (const int*)d_in[1];
    const float* W1 = (const float*)d_in[2];
    const float* b1 = (const float*)d_in[3];
    const float* W2 = (const float*)d_in[4];
    const float* b2 = (const float*)d_in[5];
    float* out = (float*)d_out;

    const int N = in_sizes[0] / D_IN;   // 50000
    const int E = in_sizes[1] / 2;      // 800000
    const int nTiles = (N + 63) / 64;   // 782

    cudaFuncSetAttribute(gin_mlp, cudaFuncAttributeMaxDynamicSharedMemorySize,
                         SMEM_BYTES);

    // zero g_h via memset node (capture-legal, no alloc)
    void* hp = nullptr;
    cudaGetSymbolAddress(&hp, g_h);
    cudaMemsetAsync(hp, 0, (size_t)N * D_IN * sizeof(float));

    gin_prep<<<128, 256>>>(W1, W2);

    int work = E * 16;
    gin_scatter<<<(work + 255) / 256, 256>>>(x, ei, E);

    gin_mlp<<<148, 512, SMEM_BYTES>>>(x, b1, b2, out, N, nTiles);
}

// round 17
// speedup vs baseline: 1.3332x; 1.0324x over previous
#include <cuda_runtime.h>
#include <cstdint>

// GIN_38216619000492: GINConv (eps=0) + 2-layer MLP.
//   h = x + segment_sum(x[src], dst);  hid = relu(h@W1+b1);  out = hid@W2+b2
// N=50000, E=800000, edge_index int32. MLP via mma.sync tf32 (base sm_100).
// R17: persistent MLP (148 CTAs, 64-row tiles, weights resident) with
// SOFTWARE-PIPELINED hs staging: next tile's x+g_h loads issue after the
// mid-bar and store after GEMM2 (hs/hid disjoint makes this legal). Weight
// prep folded into the scatter launch; g_h zeroed by a memset node.

#define D_IN  64
#define D_H   256
#define D_OUT 64
#define NMAX  50000

static __device__ float g_h[(size_t)NMAX * D_IN];
static __device__ float g_B1[17408];   // W1^T tf32 image: [n=256][k=64], stride 68
static __device__ float g_B2[16640];   // W2^T tf32 image: [n=64][k=256], stride 260

__device__ __forceinline__ uint32_t f2tf32(float f) {
    uint32_t u;
    asm("cvt.rna.tf32.f32 %0, %1;" : "=r"(u) : "f"(f));
    return u;
}

__device__ __forceinline__ void mma8(float* c, uint32_t a0, uint32_t a1,
                                     uint32_t a2, uint32_t a3,
                                     uint32_t b0, uint32_t b1) {
    asm volatile(
        "mma.sync.aligned.m16n8k8.row.col.f32.tf32.tf32.f32 "
        "{%0,%1,%2,%3}, {%4,%5,%6,%7}, {%8,%9}, {%0,%1,%2,%3};"
        : "+f"(c[0]), "+f"(c[1]), "+f"(c[2]), "+f"(c[3])
        : "r"(a0), "r"(a1), "r"(a2), "r"(a3), "r"(b0), "r"(b1));
}

// ---------------------------------------------------------------------------
// Kernel 1: scatter-add (R13-proven, at the L2 RED-op floor) + weight prep
// piggy-backed on the first 32768 threads (hidden under the 12.8M-thread
// scatter; prep completes before gin_mlp by stream order).
// ---------------------------------------------------------------------------
__global__ void gin_scatter(const float* __restrict__ x,
                            const int* __restrict__ ei, int E,
                            const float* __restrict__ W1,
                            const float* __restrict__ W2) {
    int w = blockIdx.x * blockDim.x + threadIdx.x;
    if (w < 32768) {
        if (w < 16384) {                    // W1[k][n], k<64, n<256
            int k = w >> 8, n = w & 255;
            ((uint32_t*)g_B1)[n * 68 + k] = f2tf32(W1[w]);
        } else {                            // W2[k][n], k<256, n<64
            int j = w - 16384;
            int k = j >> 6, n = j & 63;
            ((uint32_t*)g_B2)[n * 260 + k] = f2tf32(W2[j]);
        }
    }
    int e = w >> 4;
    if (e >= E) return;
    int c = (w & 15) << 2;
    int src = ei[e];
    int dst = ei[E + e];
    float4 v = *(const float4*)(x + (size_t)src * D_IN + c);
    float* o = g_h + (size_t)dst * D_IN + c;
    asm volatile("red.global.add.v4.f32 [%0], {%1, %2, %3, %4};"
                 :: "l"(o), "f"(v.x), "f"(v.y), "f"(v.z), "f"(v.w)
                 : "memory");
}

// ---------------------------------------------------------------------------
// Kernel 2: PERSISTENT pipelined MLP. 148 CTAs x 512 thr; 64-row tiles,
// grid-stride over 782. Weights resident. Per tile:
//   GEMM1 -> epi1(hid) -> BAR -> [issue next-hs LDGs] -> GEMM2 ->
//   [cvt+STS next-hs] -> epi2(out) -> BAR
// Warp w: mq=w&3 (rows [16mq,+16)), nc=w>>2
//   GEMM1 cols [64nc,+64); GEMM2 cols [16nc,+16).
// SMEM (floats, disjoint, 55,360 w = 221,440 B):
//   B1 @0 [256][68]; B2 @17408 [64][260]; b1s @34048; b2s @34304;
//   hs @34368 [64][68]; hid @38720 [64][260].
// ---------------------------------------------------------------------------
#define B1_F    0
#define B2_F    17408
#define B1S_F   34048
#define B2S_F   34304
#define HS_F    34368
#define HID_F   38720
#define SMEM_BYTES (55360 * 4)
#define GRID_P  148

__global__ __launch_bounds__(512, 1)
void gin_mlp(const float* __restrict__ x,
             const float* __restrict__ b1, const float* __restrict__ b2,
             float* __restrict__ out, int N, int nTiles) {
    extern __shared__ float s[];
    uint32_t* su = (uint32_t*)s;

    const int t = threadIdx.x;
    const int w = t >> 5;
    const int mq = w & 3;
    const int nc = w >> 2;
    const int lane = t & 31;
    const int g = lane >> 2;
    const int tg = lane & 3;

    // per-thread staging coords (2 chunks: i = t, t+512)
    const int r0c = t >> 4,        k40 = (t & 15) << 2;
    const int r1c = (t + 512) >> 4, k41 = ((t + 512) & 15) << 2;

    // ---- Stage weights + biases ONCE ----
    {
        const float4* g1 = (const float4*)g_B1;
        const float4* g2 = (const float4*)g_B2;
        float4* s1 = (float4*)(s + B1_F);
        float4* s2 = (float4*)(s + B2_F);
        for (int i = t; i < 4352; i += 512) s1[i] = g1[i];
        for (int i = t; i < 4160; i += 512) s2[i] = g2[i];
        if (t < 64) ((float4*)(s + B1S_F))[t] = ((const float4*)b1)[t];
        if (t < 16) ((float4*)(s + B2S_F))[t] = ((const float4*)b2)[t];
    }

    // ---- Stage hs for the first tile ----
    {
        const int row0 = blockIdx.x * 64;
        #pragma unroll
        for (int c = 0; c < 2; c++) {
            int r = c ? r1c : r0c, k4 = c ? k41 : k40;
            float4 v = make_float4(0.f, 0.f, 0.f, 0.f);
            int gr = row0 + r;
            if (gr < N) {
                float4 xv = *(const float4*)(x   + (size_t)gr * D_IN + k4);
                float4 hv = *(const float4*)(g_h + (size_t)gr * D_IN + k4);
                v = make_float4(xv.x + hv.x, xv.y + hv.y, xv.z + hv.z, xv.w + hv.w);
            }
            *(uint4*)(s + HS_F + r * 68 + k4) =
                make_uint4(f2tf32(v.x), f2tf32(v.y), f2tf32(v.z), f2tf32(v.w));
        }
    }
    __syncthreads();

    // invariant pointers
    const uint32_t* arow_lo1 = su + HS_F + (16 * mq + g) * 68;
    const uint32_t* arow_hi1 = arow_lo1 + 8 * 68;
    const uint32_t* Bb1 = su + B1_F + (nc * 64 + g) * 68;
    const uint32_t* arow_lo2 = su + HID_F + (16 * mq + g) * 260;
    const uint32_t* arow_hi2 = arow_lo2 + 8 * 260;
    const uint32_t* Bb2 = su + B2_F + (nc * 16 + g) * 260;

    for (int tile = blockIdx.x; tile < nTiles; tile += GRID_P) {
        const int row0 = tile * 64;
        const int nxt = tile + GRID_P;
        const bool hasNext = nxt < nTiles;

        // ---- GEMM1: rows [16mq,+16) x cols [64nc,+64) ----
        float acc[8][4];
        #pragma unroll
        for (int nt = 0; nt < 8; nt++)
            #pragma unroll
            for (int j = 0; j < 4; j++) acc[nt][j] = 0.f;

        #pragma unroll
        for (int ks = 0; ks < 8; ks++) {
            int kb = ks * 8;
            uint32_t a0 = arow_lo1[kb + tg];
            uint32_t a1 = arow_hi1[kb + tg];
            uint32_t a2 = arow_lo1[kb + tg + 4];
            uint32_t a3 = arow_hi1[kb + tg + 4];
            #pragma unroll
            for (int c4 = 0; c4 < 2; c4++) {
                uint32_t bv[4][2];
                #pragma unroll
                for (int q = 0; q < 4; q++) {
                    int ntl = c4 * 4 + q;
                    bv[q][0] = Bb1[ntl * 8 * 68 + kb + tg];
                    bv[q][1] = Bb1[ntl * 8 * 68 + kb + tg + 4];
                }
                #pragma unroll
                for (int q = 0; q < 4; q++)
                    mma8(acc[c4 * 4 + q], a0, a1, a2, a3, bv[q][0], bv[q][1]);
            }
        }

        // ---- Epilogue 1: hid = tf32(relu(D1 + b1)) ----
        {
            float* h_lo = s + HID_F + (16 * mq + g) * 260;
            float* h_hi = h_lo + 8 * 260;
            #pragma unroll
            for (int ntl = 0; ntl < 8; ntl++) {
                int col = nc * 64 + ntl * 8 + 2 * tg;
                float bb0 = s[B1S_F + col], bb1 = s[B1S_F + col + 1];
                uint2 u0, u1;
                u0.x = f2tf32(fmaxf(acc[ntl][0] + bb0, 0.f));
                u0.y = f2tf32(fmaxf(acc[ntl][1] + bb1, 0.f));
                u1.x = f2tf32(fmaxf(acc[ntl][2] + bb0, 0.f));
                u1.y = f2tf32(fmaxf(acc[ntl][3] + bb1, 0.f));
                *(uint2*)(h_lo + col) = u0;
                *(uint2*)(h_hi + col) = u1;
            }
        }
        __syncthreads();   // hs fully read (GEMM1 done); hid ready for GEMM2

        // ---- Issue next tile's staging loads (latency hides under GEMM2) ----
        float4 px0, ph0, px1, ph1;
        px0 = ph0 = px1 = ph1 = make_float4(0.f, 0.f, 0.f, 0.f);
        if (hasNext) {
            int base = nxt * 64;
            int gr0 = base + r0c, gr1 = base + r1c;
            if (gr0 < N) {
                px0 = *(const float4*)(x   + (size_t)gr0 * D_IN + k40);
                ph0 = *(const float4*)(g_h + (size_t)gr0 * D_IN + k40);
            }
            if (gr1 < N) {
                px1 = *(const float4*)(x   + (size_t)gr1 * D_IN + k41);
                ph1 = *(const float4*)(g_h + (size_t)gr1 * D_IN + k41);
            }
        }

        // ---- GEMM2: rows [16mq,+16) x cols [16nc,+16) ----
        float acc2[2][4];
        #pragma unroll
        for (int nt = 0; nt < 2; nt++)
            #pragma unroll
            for (int j = 0; j < 4; j++) acc2[nt][j] = 0.f;

        #pragma unroll 4
        for (int ks = 0; ks < 32; ks++) {
            int kb = ks * 8;
            uint32_t a0 = arow_lo2[kb + tg];
            uint32_t a1 = arow_hi2[kb + tg];
            uint32_t a2 = arow_lo2[kb + tg + 4];
            uint32_t a3 = arow_hi2[kb + tg + 4];
            uint32_t bv[2][2];
            #pragma unroll
            for (int q = 0; q < 2; q++) {
                bv[q][0] = Bb2[q * 8 * 260 + kb + tg];
                bv[q][1] = Bb2[q * 8 * 260 + kb + tg + 4];
            }
            #pragma unroll
            for (int q = 0; q < 2; q++)
                mma8(acc2[q], a0, a1, a2, a3, bv[q][0], bv[q][1]);
        }

        // ---- Store next tile's hs (loads have completed under GEMM2) ----
        if (hasNext) {
            *(uint4*)(s + HS_F + r0c * 68 + k40) = make_uint4(
                f2tf32(px0.x + ph0.x), f2tf32(px0.y + ph0.y),
                f2tf32(px0.z + ph0.z), f2tf32(px0.w + ph0.w));
            *(uint4*)(s + HS_F + r1c * 68 + k41) = make_uint4(
                f2tf32(px1.x + ph1.x), f2tf32(px1.y + ph1.y),
                f2tf32(px1.z + ph1.z), f2tf32(px1.w + ph1.w));
        }

        // ---- Epilogue 2: out = D2 + b2 (fp32) ----
        {
            int gr_lo = row0 + 16 * mq + g;
            int gr_hi = gr_lo + 8;
            #pragma unroll
            for (int ntl = 0; ntl < 2; ntl++) {
                int col = nc * 16 + ntl * 8 + 2 * tg;
                float bb0 = s[B2S_F + col], bb1 = s[B2S_F + col + 1];
                if (gr_lo < N) {
                    float2 v = make_float2(acc2[ntl][0] + bb0, acc2[ntl][1] + bb1);
                    *(float2*)(out + (size_t)gr_lo * D_OUT + col) = v;
                }
                if (gr_hi < N) {
                    float2 v = make_float2(acc2[ntl][2] + bb0, acc2[ntl][3] + bb1);
                    *(float2*)(out + (size_t)gr_hi * D_OUT + col) = v;
                }
            }
        }
        __syncthreads();   // next-hs visible to all; hid reads done before next epi1
    }
}

// ---------------------------------------------------------------------------
// Launch. Inputs: x[f32], edge_index[i32 2xE], W1, b1, W2, b2.
// ---------------------------------------------------------------------------
extern "C" void kernel_launch(void* const* d_in, const int* in_sizes, int n_in,
                              void* d_out, int out_size) {
    const float* x  = (const float*)d_in[0];
    const int*   ei = (const int*)d_in[1];
    const float* W1 = (const float*)d_in[2];
    const float* b1 = (const float*)d_in[3];
    const float* W2 = (const float*)d_in[4];
    const float* b2 = (const float*)d_in[5];
    float* out = (float*)d_out;

    const int N = in_sizes[0] / D_IN;   // 50000
    const int E = in_sizes[1] / 2;      // 800000
    const int nTiles = (N + 63) / 64;   // 782

    cudaFuncSetAttribute(gin_mlp, cudaFuncAttributeMaxDynamicSharedMemorySize,
                         SMEM_BYTES);

    // zero g_h via memset node (capture-legal, no alloc)
    void* hp = nullptr;
    cudaGetSymbolAddress(&hp, g_h);
    cudaMemsetAsync(hp, 0, (size_t)N * D_IN * sizeof(float));

    int work = E * 16;
    gin_scatter<<<(work + 255) / 256, 256>>>(x, ei, E, W1, W2);

    gin_mlp<<<GRID_P, 512, SMEM_BYTES>>>(x, b1, b2, out, N, nTiles);
}